// round 11
// baseline (speedup 1.0000x reference)
#include <cuda_runtime.h>
#include <cuda_fp16.h>
#include <cstdint>

#define IN_DIM   32768
#define CLASSES  100
#define BATCH    4096
#define NPAD     112
#define SPLITS   8
#define KSPLIT   (IN_DIM / SPLITS)       // 4096
#define KSTAGE   64
#define NITER    (KSPLIT / KSTAGE)       // 64
#define ABYTES   (128 * 128)             // 16384
#define BBYTES   (NPAD * 128)            // 14336
#define STAGE_BYTES (ABYTES + BBYTES)    // 30720
#define THREADS  256

#define SWZ(o) ((o) ^ (((o) >> 3) & 0x70))

__device__ __half g_signW[(size_t)NPAD * IN_DIM];            // 7.3 MB fp16 sign(W), padded
__device__ float  g_partial[(size_t)SPLITS * BATCH * NPAD];  // 14.7 MB split-K partials

// ---------------------------------------------------------------- helpers
__device__ __forceinline__ uint32_t smem_u32(const void* p) {
    uint32_t a;
    asm("{ .reg .u64 t; cvta.to.shared.u64 t, %1; cvt.u32.u64 %0, t; }" : "=r"(a) : "l"(p));
    return a;
}
__device__ __forceinline__ void ldsm_x4(uint32_t& r0, uint32_t& r1, uint32_t& r2, uint32_t& r3,
                                        uint32_t addr) {
    asm volatile("ldmatrix.sync.aligned.m8n8.x4.shared.b16 {%0,%1,%2,%3}, [%4];"
                 : "=r"(r0), "=r"(r1), "=r"(r2), "=r"(r3) : "r"(addr));
}
// fp16-accumulate MMA, C = 0 (chunk start): writes d fresh
__device__ __forceinline__ void mma_f16_zero(uint32_t& d0, uint32_t& d1,
                                             uint32_t a0, uint32_t a1, uint32_t a2, uint32_t a3,
                                             uint32_t b0, uint32_t b1) {
    asm volatile(
        "mma.sync.aligned.m16n8k16.row.col.f16.f16.f16.f16 "
        "{%0,%1}, {%2,%3,%4,%5}, {%6,%7}, {%8,%9};"
        : "=r"(d0), "=r"(d1)
        : "r"(a0), "r"(a1), "r"(a2), "r"(a3), "r"(b0), "r"(b1), "r"(0u), "r"(0u));
}
// fp16-accumulate MMA, C = D (chunk continue)
__device__ __forceinline__ void mma_f16_acc(uint32_t& d0, uint32_t& d1,
                                            uint32_t a0, uint32_t a1, uint32_t a2, uint32_t a3,
                                            uint32_t b0, uint32_t b1) {
    asm volatile(
        "mma.sync.aligned.m16n8k16.row.col.f16.f16.f16.f16 "
        "{%0,%1}, {%2,%3,%4,%5}, {%6,%7}, {%0,%1};"
        : "+r"(d0), "+r"(d1)
        : "r"(a0), "r"(a1), "r"(a2), "r"(a3), "r"(b0), "r"(b1));
}
__device__ __forceinline__ uint32_t hadd2u(uint32_t a, uint32_t b) {
    __half2 r = __hadd2(*reinterpret_cast<__half2*>(&a), *reinterpret_cast<__half2*>(&b));
    return *reinterpret_cast<uint32_t*>(&r);
}
__device__ __forceinline__ void sts128(uint32_t addr, uint32_t u0, uint32_t u1,
                                       uint32_t u2, uint32_t u3) {
    asm volatile("st.shared.v4.b32 [%0], {%1,%2,%3,%4};"
                 :: "r"(addr), "r"(u0), "r"(u1), "r"(u2), "r"(u3) : "memory");
}
__device__ __forceinline__ void cpasync16(uint32_t saddr, const void* gptr) {
    asm volatile("cp.async.cg.shared.global [%0], [%1], 16;"
                 :: "r"(saddr), "l"(gptr) : "memory");
}
__device__ __forceinline__ uint32_t packh2(float lo, float hi) {
    __half2 h = __floats2half2_rn(lo, hi);
    return *reinterpret_cast<uint32_t*>(&h);
}

// ---------------------------------------------------------------- kernel 1: sign(W) -> fp16
__global__ void sign_kernel(const float* __restrict__ W) {
    int i = blockIdx.x * 256 + threadIdx.x;      // granule = 8 elements
    int n  = i >> 12;
    int k8 = i & 4095;
    __half2 h[4];
    if (n < CLASSES) {
        const float4* p = reinterpret_cast<const float4*>(W + ((size_t)n << 15)) + k8 * 2;
        float4 f0 = p[0], f1 = p[1];
        #define SG(v) ((v) > 0.f ? 1.f : ((v) < 0.f ? -1.f : 0.f))
        h[0] = __floats2half2_rn(SG(f0.x), SG(f0.y));
        h[1] = __floats2half2_rn(SG(f0.z), SG(f0.w));
        h[2] = __floats2half2_rn(SG(f1.x), SG(f1.y));
        h[3] = __floats2half2_rn(SG(f1.z), SG(f1.w));
        #undef SG
    } else {
        h[0] = h[1] = h[2] = h[3] = __floats2half2_rn(0.f, 0.f);
    }
    *reinterpret_cast<float4*>(g_signW + (size_t)i * 8) = *reinterpret_cast<float4*>(h);
}

// ---------------------------------------------------------------- kernel 2: split-K fp16 GEMM
__global__ __launch_bounds__(THREADS, 2)
void binmm_kernel(const float* __restrict__ x) {
    extern __shared__ char smraw[];
    uint32_t sb = (smem_u32(smraw) + 1023u) & ~1023u;

    const int tid  = threadIdx.x;
    const int lane = tid & 31;
    const int w    = tid >> 5;
    const int bid  = blockIdx.x;
    const int mtile = bid & 31;
    const int split = bid >> 5;                  // 0..7
    const size_t m0 = (size_t)mtile * 128;
    const int kbase = split * KSPLIT;

    // ---- producer geometry (per thread) ----
    const float* pA[4];
    uint32_t sA[4];
    const __half* pB[4];
    bool bAct[4];
    #pragma unroll
    for (int j = 0; j < 4; j++) {
        int g = tid + THREADS * j;               // A: 1024 granules of 16B smem (8 halves)
        int row = g >> 3, c16 = g & 7;
        pA[j] = x + (m0 + (size_t)row) * IN_DIM + kbase + c16 * 8;
        sA[j] = SWZ((uint32_t)(row * 128 + c16 * 16));
        bAct[j] = g < (NPAD * 8);                // B: 896 granules
        pB[j] = g_signW + (size_t)row * IN_DIM + kbase + c16 * 8;
    }

    // ---- ldmatrix base addresses ----
    const int lm = lane >> 3, lr = lane & 7;
    const int arow = 16 * w + ((lm & 1) ? 8 : 0) + lr;
    const uint32_t aOff = SWZ((uint32_t)(arow * 128 + (lm >> 1) * 16));
    const int brow = ((lm & 1) ? 8 : 0) + lr;
    const uint32_t bOff = SWZ((uint32_t)(brow * 128 + (lm >> 1) * 16));

    float acc[14][4];
    uint32_t mid0[14], mid1[14];
    #pragma unroll
    for (int t = 0; t < 14; t++) {
        acc[t][0] = acc[t][1] = acc[t][2] = acc[t][3] = 0.f;
        mid0[t] = 0u; mid1[t] = 0u;
    }

    float4 fa[4];   // HALF of an A-stage in flight (16 regs)

    #define LOADA2(it, h) do {                                                    \
        _Pragma("unroll")                                                         \
        for (int j = 0; j < 2; j++) {                                             \
            const float* _p = pA[2 * (h) + j] + (size_t)(it) * KSTAGE;            \
            fa[j * 2]     = *reinterpret_cast<const float4*>(_p);                 \
            fa[j * 2 + 1] = *reinterpret_cast<const float4*>(_p + 4);             \
        }                                                                         \
    } while (0)

    #define STSA2(soff, h) do {                                                   \
        _Pragma("unroll")                                                         \
        for (int j = 0; j < 2; j++) {                                             \
            float4 f0 = fa[j * 2], f1 = fa[j * 2 + 1];                            \
            sts128(sb + (soff) + sA[2 * (h) + j],                                 \
                   packh2(f0.x, f0.y), packh2(f0.z, f0.w),                        \
                   packh2(f1.x, f1.y), packh2(f1.z, f1.w));                       \
        }                                                                         \
    } while (0)

    #define CPB(it, soff) do {                                                    \
        _Pragma("unroll")                                                         \
        for (int j = 0; j < 4; j++)                                               \
            if (bAct[j])                                                          \
                cpasync16(sb + (soff) + ABYTES + sA[j], pB[j] + (size_t)(it) * KSTAGE); \
    } while (0)

    // One K=32 chunk in fp16 accumulators, then fold into mid via HADD2.
    // c regs live only inside this macro -> no overlap with fa prefetch.
    #define COMPUTE_HALF(aA, bA, tlo) do {                                        \
        uint32_t c0[14], c1[14];                                                  \
        _Pragma("unroll")                                                         \
        for (int t = (tlo); t < (tlo) + 2; t++) {                                 \
            uint32_t a0, a1, a2, a3;                                              \
            ldsm_x4(a0, a1, a2, a3, (aA) ^ (32u * t));                            \
            _Pragma("unroll")                                                     \
            for (int p = 0; p < 7; p++) {                                         \
                uint32_t b0, b1, b2, b3;                                          \
                ldsm_x4(b0, b1, b2, b3, ((bA) + p * 2048) ^ (32u * t));           \
                if (t == (tlo)) {                                                 \
                    mma_f16_zero(c0[2 * p], c1[2 * p], a0, a1, a2, a3, b0, b2);   \
                    mma_f16_zero(c0[2 * p + 1], c1[2 * p + 1], a0, a1, a2, a3, b1, b3); \
                } else {                                                          \
                    mma_f16_acc(c0[2 * p], c1[2 * p], a0, a1, a2, a3, b0, b2);    \
                    mma_f16_acc(c0[2 * p + 1], c1[2 * p + 1], a0, a1, a2, a3, b1, b3); \
                }                                                                 \
            }                                                                     \
        }                                                                         \
        _Pragma("unroll")                                                         \
        for (int t = 0; t < 14; t++) {                                            \
            mid0[t] = hadd2u(mid0[t], c0[t]);                                     \
            mid1[t] = hadd2u(mid1[t], c1[t]);                                     \
        }                                                                         \
    } while (0)

    // ---- prologue: stages 0 and 1 ----
    LOADA2(0, 0); STSA2(0, 0); LOADA2(0, 1); STSA2(0, 1); CPB(0, 0);
    asm volatile("cp.async.commit_group;" ::: "memory");
    LOADA2(1, 0); STSA2(STAGE_BYTES, 0); LOADA2(1, 1); STSA2(STAGE_BYTES, 1);
    CPB(1, STAGE_BYTES);
    asm volatile("cp.async.commit_group;" ::: "memory");

    // ---- mainloop ----
    int s = 0;
    for (int i = 0; i < NITER; i++) {
        asm volatile("cp.async.wait_group 1;" ::: "memory");
        __syncthreads();

        const bool pf = (i + 2) < NITER;
        int s2 = s + 2; if (s2 >= 3) s2 -= 3;
        const uint32_t soff  = (uint32_t)s * STAGE_BYTES;
        const uint32_t soff2 = (uint32_t)s2 * STAGE_BYTES;

        if (pf) {
            LOADA2(i + 2, 0);
            CPB(i + 2, soff2);
        }
        asm volatile("cp.async.commit_group;" ::: "memory");

        const uint32_t aA = sb + soff + aOff;
        const uint32_t bA = sb + soff + ABYTES + bOff;

        COMPUTE_HALF(aA, bA, 0);
        if (pf) { STSA2(soff2, 0); LOADA2(i + 2, 1); }
        COMPUTE_HALF(aA, bA, 2);
        if (pf) STSA2(soff2, 1);

        // promote mid (fp16, K<=256) into fp32 every 4 iterations
        if ((i & 3) == 3) {
            #pragma unroll
            for (int t = 0; t < 14; t++) {
                float2 f0 = __half22float2(*reinterpret_cast<__half2*>(&mid0[t]));
                float2 f1 = __half22float2(*reinterpret_cast<__half2*>(&mid1[t]));
                acc[t][0] += f0.x; acc[t][1] += f0.y;
                acc[t][2] += f1.x; acc[t][3] += f1.y;
                mid0[t] = 0u; mid1[t] = 0u;
            }
        }

        if (++s == 3) s = 0;
    }

    // ---- epilogue: store split-K partials (NITER%4==0 -> mid already drained) ----
    const int r0 = 16 * w + (lane >> 2);
    #pragma unroll
    for (int nt = 0; nt < 14; nt++) {
        int n = nt * 8 + (lane & 3) * 2;
        size_t idx = ((size_t)split * BATCH + m0 + r0) * NPAD + n;
        *reinterpret_cast<float2*>(&g_partial[idx]) = make_float2(acc[nt][0], acc[nt][1]);
        *reinterpret_cast<float2*>(&g_partial[idx + 8 * NPAD]) = make_float2(acc[nt][2], acc[nt][3]);
    }
    #undef LOADA2
    #undef STSA2
    #undef CPB
    #undef COMPUTE_HALF
}

// ---------------------------------------------------------------- kernel 3: split-K reduce
__global__ void reduce_kernel(float* __restrict__ out) {
    int idx = blockIdx.x * 256 + threadIdx.x;   // BATCH * CLASSES
    int m = idx / CLASSES;
    int n = idx - m * CLASSES;
    const float scale = 0.0055242717280199026f; // 1/sqrt(32768)
    float a = 0.f;
    #pragma unroll
    for (int s = 0; s < SPLITS; s++)
        a += g_partial[((size_t)s * BATCH + m) * NPAD + n];
    out[idx] = a * scale;
}

// ---------------------------------------------------------------- launch
extern "C" void kernel_launch(void* const* d_in, const int* in_sizes, int n_in,
                              void* d_out, int out_size) {
    const float* x = (const float*)d_in[0];
    const float* W = (const float*)d_in[1];
    float* out = (float*)d_out;

    const int SMEM_DYN = 3 * STAGE_BYTES + 1024;
    cudaFuncSetAttribute(binmm_kernel, cudaFuncAttributeMaxDynamicSharedMemorySize, SMEM_DYN);

    sign_kernel<<<(NPAD * IN_DIM / 8) / 256, 256>>>(W);
    binmm_kernel<<<SPLITS * 32, THREADS, SMEM_DYN>>>(x);
    reduce_kernel<<<(BATCH * CLASSES) / 256, 256>>>(out);
}